// round 4
// baseline (speedup 1.0000x reference)
#include <cuda_runtime.h>
#include <cstdint>

// Problem constants
#define BB 4096
#define SS 200
#define DD 64
#define HH 36
#define NROWS (BB*SS)          // 819200
#define ROWF  (SS*HH)          // 7200 floats of h per batch

// ---------------- device scratch (no allocations allowed) ----------------
// h stored TRANSPOSED per batch: g_h[b*7200 + j*200 + s]
__device__ float g_h[(size_t)NROWS * HH];     // 118 MB staged h^T
__device__ float g_part[BB * 144];            // per-block per-rowgroup [sum36|sq36]
__device__ float g_stats[72];                 // reduced sums

// packed fp32x2 FMA (FFMA2) — double-rate fp32 on sm_103a
__device__ __forceinline__ void ffma2(unsigned long long& d,
                                      unsigned long long a,
                                      unsigned long long b) {
    asm("fma.rn.f32x2 %0, %1, %2, %0;" : "+l"(d) : "l"(a), "l"(b));
}
// splat one f32 into both halves of a packed f32x2
__device__ __forceinline__ unsigned long long splat2(float h) {
    unsigned long long r;
    unsigned int hu = __float_as_uint(h);
    asm("mov.b64 %0, {%1, %1};" : "=l"(r) : "r"(hu));
    return r;
}

// ---------------- pass 1: per-batch GEMM h = hist @ M_b + u_b -------------
// grid = 4096 blocks (1 batch each), 192 threads, col-pair FFMA2 scheme.
// SMEM (35,344 B): hp half-tile [32][201] f32 | M [64][36] f32 | u[36] | cbuf[64]
#define HP_STRIDE 201
#define MS_OFF    25728
#define U_OFF     34944
#define CB_OFF    35088
#define SMEM1     35344

__global__ void __launch_bounds__(192, 4)
pass1_kernel(const float* __restrict__ hist,
             const float* __restrict__ cand,
             const float* __restrict__ W1,
             const float* __restrict__ b1)
{
    extern __shared__ unsigned char smem_raw[];
    float* hpF  = (float*)smem_raw;
    float* msm  = (float*)(smem_raw + MS_OFF);
    float* u    = (float*)(smem_raw + U_OFF);
    float* cbuf = (float*)(smem_raw + CB_OFF);

    const int tid = threadIdx.x;
    const int b   = blockIdx.x;
    const float* hb = hist + (size_t)b * (SS * DD);

    if (tid < 64) cbuf[tid] = cand[b * 64 + tid];
    __syncthreads();

    // M[k][j] = W1[64+k][j] - W1[128+k][j] + cand[k]*W1[192+k][j]  (unsplatted)
    for (int e = tid; e < 64 * 36; e += 192) {
        int k = e / 36;
        msm[e] = W1[2304 + e] - W1[4608 + e] + cbuf[k] * W1[6912 + e];
    }
    // u[j] = b1[j] + sum_k cand[k]*(W1[k][j] + W1[128+k][j])
    if (tid < 36) {
        int j = tid;
        float a = b1[j];
        #pragma unroll 8
        for (int k = 0; k < 64; k++)
            a += cbuf[k] * (W1[k * 36 + j] + W1[(128 + k) * 36 + j]);
        u[j] = a;
    }

    // warp tiling: w = wr*3 + wc ; wr = row-group (100 rows), wc = 12 cols
    const int w  = tid >> 5;
    const int l  = tid & 31;
    const int wc = w % 3;
    const int wr = w / 3;
    const int jc = wc * 12;
    const int rowbase = wr * 100;
    const bool act = (l < 25);

    unsigned long long acc[4][6];
    #pragma unroll
    for (int i = 0; i < 4; i++)
        #pragma unroll
        for (int j = 0; j < 6; j++) acc[i][j] = 0ull;

    // two k-stages of 32 over a half-size hp tile
    for (int st = 0; st < 2; st++) {
        const int kk0 = st * 32;
        // load+transpose this half: hp[k][s] = hist[s][kk0+k]
        {
            const float4* h4 = (const float4*)hb;
            for (int f = tid; f < 1600; f += 192) {
                int s = f >> 3, q = f & 7;
                float4 v = h4[s * 16 + (kk0 >> 2) + q];
                float* base = hpF + (q * 4) * HP_STRIDE + s;
                base[0]              = v.x;
                base[HP_STRIDE]      = v.y;
                base[2 * HP_STRIDE]  = v.z;
                base[3 * HP_STRIDE]  = v.w;
            }
        }
        __syncthreads();
        if (act) {
            #pragma unroll 2
            for (int k = 0; k < 32; k++) {
                const float* hrow = hpF + k * HP_STRIDE + rowbase + l;
                unsigned long long h0 = splat2(hrow[0]);
                unsigned long long h1 = splat2(hrow[25]);
                unsigned long long h2 = splat2(hrow[50]);
                unsigned long long h3 = splat2(hrow[75]);
                const ulonglong2* mp = (const ulonglong2*)(msm + (kk0 + k) * 36 + jc);
                ulonglong2 mA = mp[0];
                ulonglong2 mB = mp[1];
                ulonglong2 mC = mp[2];
                unsigned long long mm[6] = {mA.x, mA.y, mB.x, mB.y, mC.x, mC.y};
                #pragma unroll
                for (int j = 0; j < 6; j++) {
                    ffma2(acc[0][j], h0, mm[j]);
                    ffma2(acc[1][j], h1, mm[j]);
                    ffma2(acc[2][j], h2, mm[j]);
                    ffma2(acc[3][j], h3, mm[j]);
                }
            }
        }
        __syncthreads();
    }

    // epilogue per column-pair: bias, stats, store h^T (coalesced STG.32)
    float* dst = g_h + (size_t)b * ROWF;
    const int pbase = b * 144 + wr * 72;
    #pragma unroll
    for (int j = 0; j < 6; j++) {
        float sLo = 0.f, sHi = 0.f, qLo = 0.f, qHi = 0.f;
        if (act) {
            const float uLo = u[jc + 2 * j];
            const float uHi = u[jc + 2 * j + 1];
            #pragma unroll
            for (int i = 0; i < 4; i++) {
                float lo = __uint_as_float((unsigned)(acc[i][j] & 0xffffffffull)) + uLo;
                float hi = __uint_as_float((unsigned)(acc[i][j] >> 32)) + uHi;
                sLo += lo; qLo += lo * lo;
                sHi += hi; qHi += hi * hi;
                int row = rowbase + i * 25 + l;
                dst[(jc + 2 * j) * SS + row]     = lo;
                dst[(jc + 2 * j + 1) * SS + row] = hi;
            }
        }
        #pragma unroll
        for (int off = 16; off > 0; off >>= 1) {
            sLo += __shfl_down_sync(0xffffffffu, sLo, off);
            qLo += __shfl_down_sync(0xffffffffu, qLo, off);
            sHi += __shfl_down_sync(0xffffffffu, sHi, off);
            qHi += __shfl_down_sync(0xffffffffu, qHi, off);
        }
        if (l == 0) {
            g_part[pbase + jc + 2 * j]          = sLo;
            g_part[pbase + 36 + jc + 2 * j]     = qLo;
            g_part[pbase + jc + 2 * j + 1]      = sHi;
            g_part[pbase + 36 + jc + 2 * j + 1] = qHi;
        }
    }
}

// ---------------- pass 2: reduce stat partials (deterministic) ------------
__global__ void __launch_bounds__(256)
reduce_stats_kernel()
{
    __shared__ float red[256];
    const int r   = blockIdx.x;      // 0..71
    const int tid = threadIdx.x;
    float s = 0.f;
    for (int b = tid; b < BB; b += 256)
        s += g_part[b * 144 + r] + g_part[b * 144 + 72 + r];
    red[tid] = s;
    __syncthreads();
    #pragma unroll
    for (int o = 128; o > 0; o >>= 1) {
        if (tid < o) red[tid] += red[tid + o];
        __syncthreads();
    }
    if (tid == 0) g_stats[r] = red[0];
}

// ---------------- pass 3: BN + Dice + W2 + weighted pooling ---------------
__global__ void __launch_bounds__(256)
pass3_kernel(const float* __restrict__ hist,
             const float* __restrict__ gamma,
             const float* __restrict__ beta,
             const float* __restrict__ alpha,
             const float* __restrict__ W2,
             const float* __restrict__ b2,
             float* __restrict__ out)
{
    __shared__ float wrow[SS];
    __shared__ float acoef[36], ccoef[36], w2s[36];
    __shared__ float4 pool4[256];

    const int tid = threadIdx.x;
    const int b   = blockIdx.x;

    if (tid < 36) {
        float sm = g_stats[tid];
        float sq = g_stats[36 + tid];
        const float invN = 1.0f / (float)NROWS;
        float mu   = sm * invN;
        float var  = sq * invN - mu * mu;
        float rstd = rsqrtf(var + 1e-5f);
        float a    = gamma[tid] * rstd;
        acoef[tid] = a;
        ccoef[tid] = beta[tid] - mu * a;
        w2s[tid]   = W2[tid];
    }
    const float alph = alpha[0];
    const float b2v  = b2[0];
    __syncthreads();

    if (tid < SS) {
        const int s = tid;
        const float* hT = g_h + (size_t)b * ROWF;  // [j][s]
        float hn[36];
        float mean = 0.f;
        #pragma unroll
        for (int j = 0; j < 36; j++) {
            float v = acoef[j] * __ldg(hT + j * SS + s) + ccoef[j];
            hn[j] = v;
            mean += v;
        }
        mean *= (1.0f / 36.0f);
        float var = 0.f;
        #pragma unroll
        for (int j = 0; j < 36; j++) {
            float d = hn[j] - mean;
            var += d * d;
        }
        var *= (1.0f / 36.0f);
        float rs = rsqrtf(var + 1e-3f);
        float wa = 0.f;
        #pragma unroll
        for (int j = 0; j < 36; j++) {
            float x  = (hn[j] - mean) * rs;
            float ps = 1.0f / (1.0f + __expf(-x));
            float hv = hn[j] * (ps + (1.0f - ps) * alph);
            wa += hv * w2s[j];
        }
        wrow[s] = wa + b2v;
    }
    __syncthreads();

    // weighted pooling (float4): out[b][d] = sum_s wrow[s] * hist[b][s][d]
    const float4* hb4 = (const float4*)(hist + (size_t)b * (SS * DD)); // [200][16]
    const int d4 = tid & 15;
    const int q  = tid >> 4;          // 0..15
    float4 a = make_float4(0.f, 0.f, 0.f, 0.f);
    for (int s = q; s < SS; s += 16) {
        float  wv = wrow[s];
        float4 v  = hb4[s * 16 + d4];
        a.x += wv * v.x; a.y += wv * v.y; a.z += wv * v.z; a.w += wv * v.w;
    }
    pool4[tid] = a;
    __syncthreads();
    if (tid < 64) {
        // stage 1: 64 threads fold 4 groups each
        int g0 = (tid >> 4) * 4;           // 0,4,8,12
        int dd = tid & 15;
        float4 t = pool4[g0 * 16 + dd];
        #pragma unroll
        for (int g = 1; g < 4; g++) {
            float4 v = pool4[(g0 + g) * 16 + dd];
            t.x += v.x; t.y += v.y; t.z += v.z; t.w += v.w;
        }
        pool4[g0 * 16 + dd] = t;
    }
    __syncthreads();
    if (tid < 16) {
        float4 t = pool4[tid];
        #pragma unroll
        for (int g = 1; g < 4; g++) {
            float4 v = pool4[g * 4 * 16 + tid];
            t.x += v.x; t.y += v.y; t.z += v.z; t.w += v.w;
        }
        ((float4*)out)[b * 16 + tid] = t;
    }
}

// ---------------- launch ----------------
extern "C" void kernel_launch(void* const* d_in, const int* in_sizes, int n_in,
                              void* d_out, int out_size)
{
    const float* history = (const float*)d_in[0];
    const float* cand    = (const float*)d_in[1];
    const float* W1      = (const float*)d_in[2];
    const float* b1      = (const float*)d_in[3];
    const float* gamma   = (const float*)d_in[4];
    const float* beta    = (const float*)d_in[5];
    const float* alpha   = (const float*)d_in[6];
    const float* W2      = (const float*)d_in[7];
    const float* b2      = (const float*)d_in[8];
    float* out = (float*)d_out;

    cudaFuncSetAttribute(pass1_kernel,
                         cudaFuncAttributeMaxDynamicSharedMemorySize, SMEM1);

    pass1_kernel<<<BB, 192, SMEM1>>>(history, cand, W1, b1);
    reduce_stats_kernel<<<72, 256>>>();
    pass3_kernel<<<BB, 256>>>(history, gamma, beta, alpha, W2, b2, out);
}